// round 6
// baseline (speedup 1.0000x reference)
#include <cuda_runtime.h>
#include <cstdint>

#define NHALF 4096
#define TN    8192
#define D     128
#define BM    128
#define NB    (TN / BM)                 // 64
#define NTILES (NB * (NB + 1) / 2)      // 2080 lower-triangle tiles
#define PITCH 144                        // smem row pitch in BYTES (128 + 16 pad)
#define SCALE (2.0f / 16129.0f)          // inv_tau / 127^2

__device__ float    g_pn  [(size_t)TN * D];        // fp32 normalized (exact pos term)
__device__ uint32_t g_pnq [(size_t)TN * (D / 4)];  // int8-packed quantized rows
__device__ float    g_rowsum[TN];                  // sum_{j != i} exp(sim_ij)

// ---------------------------------------------------------------------------
// 1) Normalize rows; emit fp32 + int8(q=round(127 v)) copies; zero accumulators.
// ---------------------------------------------------------------------------
__global__ void normalize_kernel(const float* __restrict__ zi,
                                 const float* __restrict__ zj) {
    int warp = (blockIdx.x * blockDim.x + threadIdx.x) >> 5;
    int lane = threadIdx.x & 31;
    if (warp >= TN) return;
    const float* src = (warp < NHALF) ? (zi + (size_t)warp * D)
                                      : (zj + (size_t)(warp - NHALF) * D);
    float4 v = ((const float4*)src)[lane];
    float ss = v.x * v.x + v.y * v.y + v.z * v.z + v.w * v.w;
#pragma unroll
    for (int o = 16; o > 0; o >>= 1) ss += __shfl_xor_sync(0xffffffffu, ss, o);
    float inv = 1.0f / fmaxf(sqrtf(ss), 1e-8f);
    float4 o4 = make_float4(v.x * inv, v.y * inv, v.z * inv, v.w * inv);
    ((float4*)(g_pn + (size_t)warp * D))[lane] = o4;
    int q0 = __float2int_rn(o4.x * 127.0f);
    int q1 = __float2int_rn(o4.y * 127.0f);
    int q2 = __float2int_rn(o4.z * 127.0f);
    int q3 = __float2int_rn(o4.w * 127.0f);
    uint32_t pk = (uint32_t)(q0 & 0xff) | ((uint32_t)(q1 & 0xff) << 8)
                | ((uint32_t)(q2 & 0xff) << 16) | ((uint32_t)(q3 & 0xff) << 24);
    g_pnq[(size_t)warp * (D / 4) + lane] = pk;
    if (lane == 0) g_rowsum[warp] = 0.0f;
}

// ---------------------------------------------------------------------------
// 2) Fused int8 IMMA sim-GEMM + exp + row/col sums, lower-triangle tiles.
//    256 threads = 8 warps (2x4), warp tile 64x32, mma.sync m16n8k32.s8.
// ---------------------------------------------------------------------------
__device__ __forceinline__ void ldsm4(uint32_t& r0, uint32_t& r1,
                                      uint32_t& r2, uint32_t& r3, uint32_t addr) {
    asm volatile("ldmatrix.sync.aligned.m8n8.x4.shared.b16 {%0,%1,%2,%3}, [%4];"
                 : "=r"(r0), "=r"(r1), "=r"(r2), "=r"(r3) : "r"(addr));
}
__device__ __forceinline__ void imma16832(int* d, const uint32_t* a, const uint32_t* b) {
    asm volatile(
        "mma.sync.aligned.m16n8k32.row.col.s32.s8.s8.s32 "
        "{%0,%1,%2,%3}, {%4,%5,%6,%7}, {%8,%9}, {%0,%1,%2,%3};"
        : "+r"(d[0]), "+r"(d[1]), "+r"(d[2]), "+r"(d[3])
        : "r"(a[0]), "r"(a[1]), "r"(a[2]), "r"(a[3]), "r"(b[0]), "r"(b[1]));
}

__global__ __launch_bounds__(256, 2) void simgemm_kernel() {
    // triangular tile decode: bid -> (by, bx<=by)
    int bid = blockIdx.x;
    int by = (int)((sqrtf(8.0f * (float)bid + 1.0f) - 1.0f) * 0.5f);
    while ((by + 1) * (by + 2) / 2 <= bid) by++;
    while (by * (by + 1) / 2 > bid) by--;
    int bx = bid - by * (by + 1) / 2;
    bool diag = (bx == by);

    __shared__ uint8_t As[BM * PITCH];
    __shared__ uint8_t Bs[BM * PITCH];
    __shared__ float rsum[BM];
    __shared__ float csum[BM];

    int tid = threadIdx.x, lane = tid & 31, wid = tid >> 5;

    // ---- load tiles (int8 rows of 128B) -> smem, coalesced uint4
    const uint4* srcA = (const uint4*)g_pnq + (size_t)by * BM * 8;
    const uint4* srcB = (const uint4*)g_pnq + (size_t)bx * BM * 8;
#pragma unroll
    for (int it = 0; it < 4; it++) {
        int e = it * 256 + tid;              // uint4 index 0..1023
        int row = e >> 3, col = (e & 7) * 16;
        *(uint4*)&As[row * PITCH + col] = srcA[e];
        if (!diag) *(uint4*)&Bs[row * PITCH + col] = srcB[e];
    }
    if (tid < BM) { rsum[tid] = 0.0f; csum[tid] = 0.0f; }
    __syncthreads();

    // ---- warp tiling: 2 (M) x 4 (N) warps; warp tile 64x32
    int wm = (wid >> 2) * 64;
    int wn = (wid & 3) * 32;
    uint32_t aBase = (uint32_t)__cvta_generic_to_shared(As);
    uint32_t bBase = diag ? aBase : (uint32_t)__cvta_generic_to_shared(Bs);

    int acc[4][4][4];
#pragma unroll
    for (int mt = 0; mt < 4; mt++)
#pragma unroll
        for (int nt = 0; nt < 4; nt++)
#pragma unroll
            for (int v = 0; v < 4; v++) acc[mt][nt][v] = 0;

    int g = lane >> 3, lr8 = lane & 7;
#pragma unroll
    for (int ks = 0; ks < 4; ks++) {
        int k0 = ks * 32;                    // byte offset in K
        uint32_t a[4][4], b[4][2];
        // A frags: matrix0 rows0-7/k0, m1 rows8-15/k0, m2 rows0-7/k0+16, m3 rows8-15/k0+16
#pragma unroll
        for (int mt = 0; mt < 4; mt++) {
            int row = wm + mt * 16 + ((g & 1) << 3) + lr8;
            int col = k0 + ((g >> 1) << 4);
            ldsm4(a[mt][0], a[mt][1], a[mt][2], a[mt][3],
                  aBase + (uint32_t)(row * PITCH + col));
        }
        // B frags: one x4 covers 2 n-tiles: m0 rows0-7/k0 (b0), m1 rows0-7/k0+16 (b1),
        //          m2 rows8-15/k0 (b0'), m3 rows8-15/k0+16 (b1')
#pragma unroll
        for (int np = 0; np < 2; np++) {
            int row = wn + np * 16 + ((g >> 1) << 3) + lr8;
            int col = k0 + ((g & 1) << 4);
            uint32_t r0, r1, r2, r3;
            ldsm4(r0, r1, r2, r3, bBase + (uint32_t)(row * PITCH + col));
            b[np * 2 + 0][0] = r0; b[np * 2 + 0][1] = r1;
            b[np * 2 + 1][0] = r2; b[np * 2 + 1][1] = r3;
        }
#pragma unroll
        for (int mt = 0; mt < 4; mt++)
#pragma unroll
            for (int nt = 0; nt < 4; nt++)
                imma16832(acc[mt][nt], a[mt], b[nt]);
    }

    // ---- epilogue: exp (sim <= 2: no max needed), diagonal masked, partial sums
    int r0 = lane >> 2, c0 = (lane & 3) * 2;
    float rp[8], cp[8];
#pragma unroll
    for (int i = 0; i < 8; i++) { rp[i] = 0.0f; cp[i] = 0.0f; }

#pragma unroll
    for (int mt = 0; mt < 4; mt++) {
#pragma unroll
        for (int nt = 0; nt < 4; nt++) {
            float e0 = __expf((float)acc[mt][nt][0] * SCALE);
            float e1 = __expf((float)acc[mt][nt][1] * SCALE);
            float e2 = __expf((float)acc[mt][nt][2] * SCALE);
            float e3 = __expf((float)acc[mt][nt][3] * SCALE);
            if (diag) {
                int lr = wm + mt * 16 + r0;
                int lc = wn + nt * 8 + c0;
                if (lr == lc)         e0 = 0.0f;
                if (lr == lc + 1)     e1 = 0.0f;
                if (lr + 8 == lc)     e2 = 0.0f;
                if (lr + 8 == lc + 1) e3 = 0.0f;
            }
            rp[mt * 2 + 0] += e0 + e1;
            rp[mt * 2 + 1] += e2 + e3;
            cp[nt * 2 + 0] += e0 + e2;
            cp[nt * 2 + 1] += e1 + e3;
        }
    }

    // row reduce across lanes sharing a row (lane%4 varies)
#pragma unroll
    for (int o = 1; o <= 2; o <<= 1)
#pragma unroll
        for (int i = 0; i < 8; i++) rp[i] += __shfl_xor_sync(0xffffffffu, rp[i], o);
    if ((lane & 3) == 0) {
#pragma unroll
        for (int mt = 0; mt < 4; mt++) {
            atomicAdd(&rsum[wm + mt * 16 + r0 + 0], rp[mt * 2 + 0]);
            atomicAdd(&rsum[wm + mt * 16 + r0 + 8], rp[mt * 2 + 1]);
        }
    }
    // col reduce across lanes sharing a col (lane>>2 varies)
#pragma unroll
    for (int o = 4; o <= 16; o <<= 1)
#pragma unroll
        for (int i = 0; i < 8; i++) cp[i] += __shfl_xor_sync(0xffffffffu, cp[i], o);
    if (lane < 4) {
#pragma unroll
        for (int nt = 0; nt < 4; nt++) {
            atomicAdd(&csum[wn + nt * 8 + lane * 2 + 0], cp[nt * 2 + 0]);
            atomicAdd(&csum[wn + nt * 8 + lane * 2 + 1], cp[nt * 2 + 1]);
        }
    }
    __syncthreads();

    // ---- one global RED per row (+ per col for off-diagonal tiles)
    if (tid < BM) {
        atomicAdd(&g_rowsum[by * BM + tid], rsum[tid]);
    } else if (!diag) {
        atomicAdd(&g_rowsum[bx * BM + (tid - BM)], csum[tid - BM]);
    }
}

// ---------------------------------------------------------------------------
// 3) Finalize: loss_i = log(rowsum_i) - pos_i/tau (diag already excluded).
//    pos from exact fp32 normalized rows.
// ---------------------------------------------------------------------------
__global__ void finalize_kernel(float* __restrict__ out) {
    int warp = (blockIdx.x * blockDim.x + threadIdx.x) >> 5;
    int lane = threadIdx.x & 31;
    if (warp >= TN) return;
    int pair = (warp < NHALF) ? warp + NHALF : warp - NHALF;
    float4 v = ((const float4*)(g_pn + (size_t)warp * D))[lane];
    float4 w = ((const float4*)(g_pn + (size_t)pair * D))[lane];
    float pd = v.x * w.x + v.y * w.y + v.z * w.z + v.w * w.w;
#pragma unroll
    for (int o = 16; o > 0; o >>= 1) pd += __shfl_xor_sync(0xffffffffu, pd, o);
    if (lane == 0) {
        float val = logf(g_rowsum[warp]) - pd * 2.0f;
        atomicAdd(out, val * (1.0f / (float)TN));
    }
}

// ---------------------------------------------------------------------------
extern "C" void kernel_launch(void* const* d_in, const int* in_sizes, int n_in,
                              void* d_out, int out_size) {
    const float* zi = (const float*)d_in[0];
    const float* zj = (const float*)d_in[1];
    float* out = (float*)d_out;

    cudaMemsetAsync(out, 0, sizeof(float));
    normalize_kernel<<<TN / 8, 256>>>(zi, zj);
    simgemm_kernel<<<NTILES, 256>>>();
    finalize_kernel<<<TN / 8, 256>>>(out);
}

// round 7
// speedup vs baseline: 1.6329x; 1.6329x over previous
#include <cuda_runtime.h>
#include <cuda_bf16.h>
#include <cstdint>

#define NHALF 4096
#define TN    8192
#define D     128
#define BM    128
#define NB    (TN / BM)                 // 64
#define NTILES (NB * (NB + 1) / 2)      // 2080 lower-triangle tiles
#define PITCH 136                        // smem pitch in bf16 elems (conflict-free)

__device__ float         g_pn [(size_t)TN * D];   // fp32 normalized rows (exact pos)
__device__ __nv_bfloat16 g_pnh[(size_t)TN * D];   // bf16 copy for tensor cores
__device__ float         g_rowsum[TN];            // sum_{j != i} exp(sim_ij)

// ---------------------------------------------------------------------------
// 1) Normalize: 4 rows per warp (MLP=4), fp32 + bf16 outputs, zero rowsums.
// ---------------------------------------------------------------------------
__global__ void normalize_kernel(const float* __restrict__ zi,
                                 const float* __restrict__ zj) {
    int warp = (blockIdx.x * blockDim.x + threadIdx.x) >> 5;   // 0..2047
    int lane = threadIdx.x & 31;
    int row0 = warp * 4;
    if (row0 >= TN) return;

    float4 v[4];
#pragma unroll
    for (int r = 0; r < 4; r++) {
        int row = row0 + r;
        const float* src = (row < NHALF) ? (zi + (size_t)row * D)
                                         : (zj + (size_t)(row - NHALF) * D);
        v[r] = ((const float4*)src)[lane];
    }
#pragma unroll
    for (int r = 0; r < 4; r++) {
        float ss = v[r].x * v[r].x + v[r].y * v[r].y + v[r].z * v[r].z + v[r].w * v[r].w;
#pragma unroll
        for (int o = 16; o > 0; o >>= 1) ss += __shfl_xor_sync(0xffffffffu, ss, o);
        float inv = 1.0f / fmaxf(sqrtf(ss), 1e-8f);
        int row = row0 + r;
        float4 o4 = make_float4(v[r].x * inv, v[r].y * inv, v[r].z * inv, v[r].w * inv);
        ((float4*)(g_pn + (size_t)row * D))[lane] = o4;
        __nv_bfloat162 h0 = __floats2bfloat162_rn(o4.x, o4.y);
        __nv_bfloat162 h1 = __floats2bfloat162_rn(o4.z, o4.w);
        uint2 u;
        u.x = *reinterpret_cast<uint32_t*>(&h0);
        u.y = *reinterpret_cast<uint32_t*>(&h1);
        ((uint2*)(g_pnh + (size_t)row * D))[lane] = u;
        if (lane == 0) g_rowsum[row] = 0.0f;
    }
}

// ---------------------------------------------------------------------------
// 2) Fused bf16 HMMA sim-GEMM + exp + row/col sums, triangular tile grid.
//    256 threads = 8 warps (2x4), warp tile 64x32, mma.sync m16n8k16.
// ---------------------------------------------------------------------------
__device__ __forceinline__ void ldsm4(uint32_t& r0, uint32_t& r1,
                                      uint32_t& r2, uint32_t& r3, uint32_t addr) {
    asm volatile("ldmatrix.sync.aligned.m8n8.x4.shared.b16 {%0,%1,%2,%3}, [%4];"
                 : "=r"(r0), "=r"(r1), "=r"(r2), "=r"(r3) : "r"(addr));
}
__device__ __forceinline__ void mma16816(float* d, const uint32_t* a, const uint32_t* b) {
    asm volatile(
        "mma.sync.aligned.m16n8k16.row.col.f32.bf16.bf16.f32 "
        "{%0,%1,%2,%3}, {%4,%5,%6,%7}, {%8,%9}, {%0,%1,%2,%3};"
        : "+f"(d[0]), "+f"(d[1]), "+f"(d[2]), "+f"(d[3])
        : "r"(a[0]), "r"(a[1]), "r"(a[2]), "r"(a[3]), "r"(b[0]), "r"(b[1]));
}

__global__ __launch_bounds__(256, 2) void simgemm_kernel() {
    // triangular decode: bid -> (by, bx <= by)
    int bid = blockIdx.x;
    int by = (int)((sqrtf(8.0f * (float)bid + 1.0f) - 1.0f) * 0.5f);
    while ((by + 1) * (by + 2) / 2 <= bid) by++;
    while (by * (by + 1) / 2 > bid) by--;
    int bx = bid - by * (by + 1) / 2;
    bool diag = (bx == by);

    extern __shared__ char smem_raw[];
    __nv_bfloat16* As = (__nv_bfloat16*)smem_raw;            // [128][PITCH]
    __nv_bfloat16* Bs = As + BM * PITCH;                     // [128][PITCH]
    float* rsum = (float*)(Bs + BM * PITCH);                 // [128]
    float* csum = rsum + BM;                                 // [128]

    int tid = threadIdx.x, lane = tid & 31, wid = tid >> 5;

    // ---- load tiles, coalesced uint4; diag reuses As as Bs
    const __nv_bfloat16* srcA = g_pnh + (size_t)by * BM * D;
    const __nv_bfloat16* srcB = g_pnh + (size_t)bx * BM * D;
#pragma unroll
    for (int it = 0; it < (BM * D) / (256 * 8); it++) {
        int e = it * 2048 + tid * 8;
        int row = e >> 7, col = e & 127;
        *(uint4*)&As[row * PITCH + col] = *(const uint4*)&srcA[e];
        if (!diag) *(uint4*)&Bs[row * PITCH + col] = *(const uint4*)&srcB[e];
    }
    if (tid < BM) { rsum[tid] = 0.0f; csum[tid] = 0.0f; }
    __syncthreads();

    // ---- warp tiling: 2 (M) x 4 (N) warps; warp tile 64x32
    int wm = (wid >> 2) * 64;
    int wn = (wid & 3) * 32;
    uint32_t aTile = (uint32_t)__cvta_generic_to_shared(As);
    uint32_t bTile = diag ? aTile : (uint32_t)__cvta_generic_to_shared(Bs);

    float acc[4][4][4];
#pragma unroll
    for (int mt = 0; mt < 4; mt++)
#pragma unroll
        for (int nt = 0; nt < 4; nt++)
#pragma unroll
            for (int v = 0; v < 4; v++) acc[mt][nt][v] = 0.0f;

#pragma unroll
    for (int ks = 0; ks < 8; ks++) {
        int k0 = ks * 16;
        uint32_t a[4][4], b[4][2];
#pragma unroll
        for (int mt = 0; mt < 4; mt++) {
            int row = wm + mt * 16 + (lane & 15);
            int col = k0 + ((lane >> 4) << 3);
            ldsm4(a[mt][0], a[mt][1], a[mt][2], a[mt][3],
                  aTile + (uint32_t)(row * PITCH + col) * 2u);
        }
#pragma unroll
        for (int np = 0; np < 2; np++) {
            int g = lane >> 3;
            int row = wn + np * 16 + ((g >> 1) << 3) + (lane & 7);
            int col = k0 + ((g & 1) << 3);
            uint32_t r0, r1, r2, r3;
            ldsm4(r0, r1, r2, r3, bTile + (uint32_t)(row * PITCH + col) * 2u);
            b[np * 2 + 0][0] = r0; b[np * 2 + 0][1] = r1;
            b[np * 2 + 1][0] = r2; b[np * 2 + 1][1] = r3;
        }
#pragma unroll
        for (int mt = 0; mt < 4; mt++)
#pragma unroll
            for (int nt = 0; nt < 4; nt++)
                mma16816(acc[mt][nt], a[mt], b[nt]);
    }

    // ---- epilogue: exp (sim <= 2, no max), diagonal masked, partial sums
    int r0 = lane >> 2, c0 = (lane & 3) * 2;
    float rp[8], cp[8];
#pragma unroll
    for (int i = 0; i < 8; i++) { rp[i] = 0.0f; cp[i] = 0.0f; }

#pragma unroll
    for (int mt = 0; mt < 4; mt++) {
#pragma unroll
        for (int nt = 0; nt < 4; nt++) {
            float e0 = __expf(acc[mt][nt][0] * 2.0f);
            float e1 = __expf(acc[mt][nt][1] * 2.0f);
            float e2 = __expf(acc[mt][nt][2] * 2.0f);
            float e3 = __expf(acc[mt][nt][3] * 2.0f);
            if (diag) {
                int lr = wm + mt * 16 + r0;
                int lc = wn + nt * 8 + c0;
                if (lr == lc)         e0 = 0.0f;
                if (lr == lc + 1)     e1 = 0.0f;
                if (lr + 8 == lc)     e2 = 0.0f;
                if (lr + 8 == lc + 1) e3 = 0.0f;
            }
            rp[mt * 2 + 0] += e0 + e1;
            rp[mt * 2 + 1] += e2 + e3;
            cp[nt * 2 + 0] += e0 + e2;
            cp[nt * 2 + 1] += e1 + e3;
        }
    }

#pragma unroll
    for (int o = 1; o <= 2; o <<= 1)
#pragma unroll
        for (int i = 0; i < 8; i++) rp[i] += __shfl_xor_sync(0xffffffffu, rp[i], o);
    if ((lane & 3) == 0) {
#pragma unroll
        for (int mt = 0; mt < 4; mt++) {
            atomicAdd(&rsum[wm + mt * 16 + r0 + 0], rp[mt * 2 + 0]);
            atomicAdd(&rsum[wm + mt * 16 + r0 + 8], rp[mt * 2 + 1]);
        }
    }
#pragma unroll
    for (int o = 4; o <= 16; o <<= 1)
#pragma unroll
        for (int i = 0; i < 8; i++) cp[i] += __shfl_xor_sync(0xffffffffu, cp[i], o);
    if (lane < 4) {
#pragma unroll
        for (int nt = 0; nt < 4; nt++) {
            atomicAdd(&csum[wn + nt * 8 + lane * 2 + 0], cp[nt * 2 + 0]);
            atomicAdd(&csum[wn + nt * 8 + lane * 2 + 1], cp[nt * 2 + 1]);
        }
    }
    __syncthreads();

    if (tid < BM) {
        atomicAdd(&g_rowsum[by * BM + tid], rsum[tid]);
    } else if (!diag) {
        atomicAdd(&g_rowsum[bx * BM + (tid - BM)], csum[tid - BM]);
    }
}

// ---------------------------------------------------------------------------
// 3) Finalize: 4 rows per warp, block-level reduction, 1 global atomic / block.
//    loss_i = log(rowsum_i) - pos_i/tau (diag excluded; pos from exact fp32).
// ---------------------------------------------------------------------------
__global__ void finalize_kernel(float* __restrict__ out) {
    __shared__ float bred[8];
    int warp = (blockIdx.x * blockDim.x + threadIdx.x) >> 5;  // 0..2047
    int lane = threadIdx.x & 31, wib = (threadIdx.x >> 5);
    int row0 = warp * 4;

    float local = 0.0f;
    if (row0 < TN) {
        float4 v[4], w[4];
#pragma unroll
        for (int r = 0; r < 4; r++) {
            int row = row0 + r;
            int pair = (row < NHALF) ? row + NHALF : row - NHALF;
            v[r] = ((const float4*)(g_pn + (size_t)row * D))[lane];
            w[r] = ((const float4*)(g_pn + (size_t)pair * D))[lane];
        }
#pragma unroll
        for (int r = 0; r < 4; r++) {
            float pd = v[r].x * w[r].x + v[r].y * w[r].y + v[r].z * w[r].z + v[r].w * w[r].w;
#pragma unroll
            for (int o = 16; o > 0; o >>= 1) pd += __shfl_xor_sync(0xffffffffu, pd, o);
            if (lane == 0)
                local += logf(g_rowsum[row0 + r]) - pd * 2.0f;
        }
    }
    if (lane == 0) bred[wib] = local;
    __syncthreads();
    if (threadIdx.x == 0) {
        float s = 0.0f;
#pragma unroll
        for (int i = 0; i < 8; i++) s += bred[i];
        atomicAdd(out, s * (1.0f / (float)TN));
    }
}

// ---------------------------------------------------------------------------
extern "C" void kernel_launch(void* const* d_in, const int* in_sizes, int n_in,
                              void* d_out, int out_size) {
    const float* zi = (const float*)d_in[0];
    const float* zj = (const float*)d_in[1];
    float* out = (float*)d_out;

    cudaMemsetAsync(out, 0, sizeof(float));

    normalize_kernel<<<TN / 32, 256>>>(zi, zj);   // 2048 warps, 4 rows each

    size_t smem_bytes = (size_t)(2 * BM * PITCH) * sizeof(__nv_bfloat16)
                        + 2 * BM * sizeof(float);
    static bool attr_set = false;
    if (!attr_set) {
        cudaFuncSetAttribute(simgemm_kernel,
                             cudaFuncAttributeMaxDynamicSharedMemorySize,
                             (int)smem_bytes);
        attr_set = true;
    }
    simgemm_kernel<<<NTILES, 256, smem_bytes>>>();

    finalize_kernel<<<TN / 32, 256>>>(out);       // 2048 warps, 4 rows each
}

// round 8
// speedup vs baseline: 1.6823x; 1.0303x over previous
#include <cuda_runtime.h>
#include <cuda_bf16.h>
#include <cstdint>

#define NHALF 4096
#define TN    8192
#define D     128
#define BM    128
#define NB    (TN / BM)                 // 64
#define NTILES (NB * (NB + 1) / 2)      // 2080 lower-triangle tiles
#define PITCH 136                        // smem pitch in bf16 elems (conflict-free)

__device__ __nv_bfloat16 g_pnh[(size_t)TN * D];   // bf16 normalized rows
__device__ float         g_rowsum[TN];            // sum_{j != i} exp(sim_ij)

// ---------------------------------------------------------------------------
// 1) Normalize: 4 rows per warp (MLP=4), bf16 output only; zero rowsums + out.
// ---------------------------------------------------------------------------
__global__ void normalize_kernel(const float* __restrict__ zi,
                                 const float* __restrict__ zj,
                                 float* __restrict__ out) {
    int warp = (blockIdx.x * blockDim.x + threadIdx.x) >> 5;   // 0..2047
    int lane = threadIdx.x & 31;
    if (blockIdx.x == 0 && threadIdx.x == 0) *out = 0.0f;
    int row0 = warp * 4;
    if (row0 >= TN) return;

    float4 v[4];
#pragma unroll
    for (int r = 0; r < 4; r++) {
        int row = row0 + r;
        const float* src = (row < NHALF) ? (zi + (size_t)row * D)
                                         : (zj + (size_t)(row - NHALF) * D);
        v[r] = ((const float4*)src)[lane];
    }
#pragma unroll
    for (int r = 0; r < 4; r++) {
        float ss = v[r].x * v[r].x + v[r].y * v[r].y + v[r].z * v[r].z + v[r].w * v[r].w;
#pragma unroll
        for (int o = 16; o > 0; o >>= 1) ss += __shfl_xor_sync(0xffffffffu, ss, o);
        float inv = 1.0f / fmaxf(sqrtf(ss), 1e-8f);
        int row = row0 + r;
        __nv_bfloat162 h0 = __floats2bfloat162_rn(v[r].x * inv, v[r].y * inv);
        __nv_bfloat162 h1 = __floats2bfloat162_rn(v[r].z * inv, v[r].w * inv);
        uint2 u;
        u.x = *reinterpret_cast<uint32_t*>(&h0);
        u.y = *reinterpret_cast<uint32_t*>(&h1);
        ((uint2*)(g_pnh + (size_t)row * D))[lane] = u;
        if (lane == 0) g_rowsum[row] = 0.0f;
    }
}

// ---------------------------------------------------------------------------
// 2) Fused bf16 HMMA sim-GEMM + exp + row/col sums, triangular tile grid.
//    256 threads = 8 warps (2x4), warp tile 64x32, mma.sync m16n8k16.
// ---------------------------------------------------------------------------
__device__ __forceinline__ void ldsm4(uint32_t& r0, uint32_t& r1,
                                      uint32_t& r2, uint32_t& r3, uint32_t addr) {
    asm volatile("ldmatrix.sync.aligned.m8n8.x4.shared.b16 {%0,%1,%2,%3}, [%4];"
                 : "=r"(r0), "=r"(r1), "=r"(r2), "=r"(r3) : "r"(addr));
}
__device__ __forceinline__ void mma16816(float* d, const uint32_t* a, const uint32_t* b) {
    asm volatile(
        "mma.sync.aligned.m16n8k16.row.col.f32.bf16.bf16.f32 "
        "{%0,%1,%2,%3}, {%4,%5,%6,%7}, {%8,%9}, {%0,%1,%2,%3};"
        : "+f"(d[0]), "+f"(d[1]), "+f"(d[2]), "+f"(d[3])
        : "r"(a[0]), "r"(a[1]), "r"(a[2]), "r"(a[3]), "r"(b[0]), "r"(b[1]));
}

__global__ __launch_bounds__(256, 2) void simgemm_kernel() {
    // triangular decode: bid -> (by, bx <= by)
    int bid = blockIdx.x;
    int by = (int)((sqrtf(8.0f * (float)bid + 1.0f) - 1.0f) * 0.5f);
    while ((by + 1) * (by + 2) / 2 <= bid) by++;
    while (by * (by + 1) / 2 > bid) by--;
    int bx = bid - by * (by + 1) / 2;
    bool diag = (bx == by);

    extern __shared__ char smem_raw[];
    __nv_bfloat16* As = (__nv_bfloat16*)smem_raw;            // [128][PITCH]
    __nv_bfloat16* Bs = As + BM * PITCH;                     // [128][PITCH]
    float* rsum = (float*)(Bs + BM * PITCH);                 // [128]
    float* csum = rsum + BM;                                 // [128]

    int tid = threadIdx.x, lane = tid & 31, wid = tid >> 5;

    // ---- load tiles, coalesced uint4; diag reuses As as Bs
    const __nv_bfloat16* srcA = g_pnh + (size_t)by * BM * D;
    const __nv_bfloat16* srcB = g_pnh + (size_t)bx * BM * D;
#pragma unroll
    for (int it = 0; it < (BM * D) / (256 * 8); it++) {
        int e = it * 2048 + tid * 8;
        int row = e >> 7, col = e & 127;
        *(uint4*)&As[row * PITCH + col] = *(const uint4*)&srcA[e];
        if (!diag) *(uint4*)&Bs[row * PITCH + col] = *(const uint4*)&srcB[e];
    }
    if (tid < BM) { rsum[tid] = 0.0f; csum[tid] = 0.0f; }
    __syncthreads();

    // ---- warp tiling: 2 (M) x 4 (N) warps; warp tile 64x32
    int wm = (wid >> 2) * 64;
    int wn = (wid & 3) * 32;
    uint32_t aTile = (uint32_t)__cvta_generic_to_shared(As);
    uint32_t bTile = diag ? aTile : (uint32_t)__cvta_generic_to_shared(Bs);

    float acc[4][4][4];
#pragma unroll
    for (int mt = 0; mt < 4; mt++)
#pragma unroll
        for (int nt = 0; nt < 4; nt++)
#pragma unroll
            for (int v = 0; v < 4; v++) acc[mt][nt][v] = 0.0f;

#pragma unroll
    for (int ks = 0; ks < 8; ks++) {
        int k0 = ks * 16;
        uint32_t a[4][4], b[4][2];
#pragma unroll
        for (int mt = 0; mt < 4; mt++) {
            int row = wm + mt * 16 + (lane & 15);
            int col = k0 + ((lane >> 4) << 3);
            ldsm4(a[mt][0], a[mt][1], a[mt][2], a[mt][3],
                  aTile + (uint32_t)(row * PITCH + col) * 2u);
        }
#pragma unroll
        for (int np = 0; np < 2; np++) {
            int g = lane >> 3;
            int row = wn + np * 16 + ((g >> 1) << 3) + (lane & 7);
            int col = k0 + ((g & 1) << 3);
            uint32_t r0, r1, r2, r3;
            ldsm4(r0, r1, r2, r3, bTile + (uint32_t)(row * PITCH + col) * 2u);
            b[np * 2 + 0][0] = r0; b[np * 2 + 0][1] = r1;
            b[np * 2 + 1][0] = r2; b[np * 2 + 1][1] = r3;
        }
#pragma unroll
        for (int mt = 0; mt < 4; mt++)
#pragma unroll
            for (int nt = 0; nt < 4; nt++)
                mma16816(acc[mt][nt], a[mt], b[nt]);
    }

    // ---- epilogue: exp (sim <= 2, no max), diagonal masked, partial sums
    int r0 = lane >> 2, c0 = (lane & 3) * 2;
    float rp[8], cp[8];
#pragma unroll
    for (int i = 0; i < 8; i++) { rp[i] = 0.0f; cp[i] = 0.0f; }

#pragma unroll
    for (int mt = 0; mt < 4; mt++) {
#pragma unroll
        for (int nt = 0; nt < 4; nt++) {
            float e0 = __expf(acc[mt][nt][0] * 2.0f);
            float e1 = __expf(acc[mt][nt][1] * 2.0f);
            float e2 = __expf(acc[mt][nt][2] * 2.0f);
            float e3 = __expf(acc[mt][nt][3] * 2.0f);
            if (diag) {
                int lr = wm + mt * 16 + r0;
                int lc = wn + nt * 8 + c0;
                if (lr == lc)         e0 = 0.0f;
                if (lr == lc + 1)     e1 = 0.0f;
                if (lr + 8 == lc)     e2 = 0.0f;
                if (lr + 8 == lc + 1) e3 = 0.0f;
            }
            rp[mt * 2 + 0] += e0 + e1;
            rp[mt * 2 + 1] += e2 + e3;
            cp[nt * 2 + 0] += e0 + e2;
            cp[nt * 2 + 1] += e1 + e3;
        }
    }

#pragma unroll
    for (int o = 1; o <= 2; o <<= 1)
#pragma unroll
        for (int i = 0; i < 8; i++) rp[i] += __shfl_xor_sync(0xffffffffu, rp[i], o);
    if ((lane & 3) == 0) {
#pragma unroll
        for (int mt = 0; mt < 4; mt++) {
            atomicAdd(&rsum[wm + mt * 16 + r0 + 0], rp[mt * 2 + 0]);
            atomicAdd(&rsum[wm + mt * 16 + r0 + 8], rp[mt * 2 + 1]);
        }
    }
#pragma unroll
    for (int o = 4; o <= 16; o <<= 1)
#pragma unroll
        for (int i = 0; i < 8; i++) cp[i] += __shfl_xor_sync(0xffffffffu, cp[i], o);
    if (lane < 4) {
#pragma unroll
        for (int nt = 0; nt < 4; nt++) {
            atomicAdd(&csum[wn + nt * 8 + lane * 2 + 0], cp[nt * 2 + 0]);
            atomicAdd(&csum[wn + nt * 8 + lane * 2 + 1], cp[nt * 2 + 1]);
        }
    }
    __syncthreads();

    if (tid < BM) {
        atomicAdd(&g_rowsum[by * BM + tid], rsum[tid]);
    } else if (!diag) {
        atomicAdd(&g_rowsum[bx * BM + (tid - BM)], csum[tid - BM]);
    }
}

// ---------------------------------------------------------------------------
// 3) Finalize: 4 rows per warp; pos from bf16 rows (fp32 accumulate);
//    block reduction, 1 global atomic per block.
// ---------------------------------------------------------------------------
__global__ void finalize_kernel(float* __restrict__ out) {
    __shared__ float bred[8];
    int warp = (blockIdx.x * blockDim.x + threadIdx.x) >> 5;  // 0..2047
    int lane = threadIdx.x & 31, wib = (threadIdx.x >> 5);
    int row0 = warp * 4;

    float local = 0.0f;
    if (row0 < TN) {
        uint2 v[4], w[4];
#pragma unroll
        for (int r = 0; r < 4; r++) {
            int row = row0 + r;
            int pair = (row < NHALF) ? row + NHALF : row - NHALF;
            v[r] = ((const uint2*)(g_pnh + (size_t)row * D))[lane];
            w[r] = ((const uint2*)(g_pnh + (size_t)pair * D))[lane];
        }
#pragma unroll
        for (int r = 0; r < 4; r++) {
            __nv_bfloat162 v0 = *reinterpret_cast<__nv_bfloat162*>(&v[r].x);
            __nv_bfloat162 v1 = *reinterpret_cast<__nv_bfloat162*>(&v[r].y);
            __nv_bfloat162 w0 = *reinterpret_cast<__nv_bfloat162*>(&w[r].x);
            __nv_bfloat162 w1 = *reinterpret_cast<__nv_bfloat162*>(&w[r].y);
            float pd = __bfloat162float(v0.x) * __bfloat162float(w0.x)
                     + __bfloat162float(v0.y) * __bfloat162float(w0.y)
                     + __bfloat162float(v1.x) * __bfloat162float(w1.x)
                     + __bfloat162float(v1.y) * __bfloat162float(w1.y);
#pragma unroll
            for (int o = 16; o > 0; o >>= 1) pd += __shfl_xor_sync(0xffffffffu, pd, o);
            if (lane == 0)
                local += logf(g_rowsum[row0 + r]) - pd * 2.0f;
        }
    }
    if (lane == 0) bred[wib] = local;
    __syncthreads();
    if (threadIdx.x == 0) {
        float s = 0.0f;
#pragma unroll
        for (int i = 0; i < 8; i++) s += bred[i];
        atomicAdd(out, s * (1.0f / (float)TN));
    }
}

// ---------------------------------------------------------------------------
extern "C" void kernel_launch(void* const* d_in, const int* in_sizes, int n_in,
                              void* d_out, int out_size) {
    const float* zi = (const float*)d_in[0];
    const float* zj = (const float*)d_in[1];
    float* out = (float*)d_out;

    normalize_kernel<<<TN / 32, 256>>>(zi, zj, out);   // also zeros *out

    size_t smem_bytes = (size_t)(2 * BM * PITCH) * sizeof(__nv_bfloat16)
                        + 2 * BM * sizeof(float);
    static bool attr_set = false;
    if (!attr_set) {
        cudaFuncSetAttribute(simgemm_kernel,
                             cudaFuncAttributeMaxDynamicSharedMemorySize,
                             (int)smem_bytes);
        attr_set = true;
    }
    simgemm_kernel<<<NTILES, 256, smem_bytes>>>();

    finalize_kernel<<<TN / 32, 256>>>(out);
}